// round 10
// baseline (speedup 1.0000x reference)
#include <cuda_runtime.h>
#include <cuda_bf16.h>
#include <cstdint>
#include <math.h>
#include <float.h>

#define KCODES 8192
#define DIM    256
#define NROWS  16384

#define Q_OFF     0
#define LOSS_OFF  4194304
#define PERP_OFF  4194305
#define IDX_OFF   4194306
#define EMB_OFF   4210690

#define DECAYF 0.99f
#define OMD    ((float)(1.0 - 0.99))
#define KEPS   ((float)(8192.0 * 1e-5))
#define MARGIN 0.3f

// main-kernel smem geometry (int8 tiles, 272B padded rows -> conflict-free ldmatrix)
#define PB      272
#define M_CTA   64
#define SOFF_A  0                       // 64*272 = 17408
#define SOFF_B  17408                   // 3 bufs * 17408
#define BUFSZ   17408
#define SOFF_CE 69632                   // 3 * 512 (float2 per code: {se, esq})
#define SMEM_MAIN 71168

// ---------------- device scratch ----------------
__device__ __align__(16) char  g_Ai[(size_t)NROWS * DIM];     // 4 MB int8 rows
__device__ __align__(16) char  g_Bi[(size_t)KCODES * DIM];    // 2 MB int8 code-major
__device__ __align__(16) float g_ET[(size_t)KCODES * DIM];    // 8 MB fp32 code-major (exact rescore)
__device__ float g_sx[NROWS];                                  // per-row x scale (max/127)
__device__ float g_se[KCODES];                                 // per-code quant scale (127/max)
__device__ __align__(16) float2 g_ce[KCODES];                  // {max/127, esq}
__device__ float g_esq[KCODES];
__device__ float g_dw[DIM * KCODES];
__device__ float g_counts[KCODES];
__device__ float g_scale[KCODES];
__device__ float g_loss;

// ---------------- PTX helpers (baseline compute_103 only) ----------------
__device__ __forceinline__ uint32_t s2u(const void* p) {
    uint32_t a;
    asm("{ .reg .u64 t; cvta.to.shared.u64 t, %1; cvt.u32.u64 %0, t; }" : "=r"(a) : "l"(p));
    return a;
}
__device__ __forceinline__ void cpa16(uint32_t dst, const void* src) {
    asm volatile("cp.async.cg.shared.global [%0], [%1], 16;" :: "r"(dst), "l"(src) : "memory");
}
__device__ __forceinline__ void cpcommit() {
    asm volatile("cp.async.commit_group;" ::: "memory");
}
template <int N> __device__ __forceinline__ void cpwait() {
    asm volatile("cp.async.wait_group %0;" :: "n"(N) : "memory");
}
__device__ __forceinline__ void ldsm4(unsigned& r0, unsigned& r1, unsigned& r2, unsigned& r3,
                                      uint32_t a) {
    asm volatile("ldmatrix.sync.aligned.m8n8.x4.shared.b16 {%0,%1,%2,%3},[%4];"
                 : "=r"(r0), "=r"(r1), "=r"(r2), "=r"(r3) : "r"(a));
}
__device__ __forceinline__ void mma_s8(int (&d)[4], const unsigned (&a)[4],
                                       const unsigned b0, const unsigned b1) {
    asm volatile("mma.sync.aligned.m16n8k32.row.col.s32.s8.s8.s32 "
                 "{%0,%1,%2,%3},{%4,%5,%6,%7},{%8,%9},{%0,%1,%2,%3};"
                 : "+r"(d[0]), "+r"(d[1]), "+r"(d[2]), "+r"(d[3])
                 : "r"(a[0]), "r"(a[1]), "r"(a[2]), "r"(a[3]), "r"(b0), "r"(b1));
}
__device__ __forceinline__ void top4(float s, int k, float (&S)[4], int (&I)[4]) {
    if (s > S[3]) {
        if (s > S[1]) {
            if (s > S[0]) {
                S[3] = S[2]; I[3] = I[2]; S[2] = S[1]; I[2] = I[1];
                S[1] = S[0]; I[1] = I[0]; S[0] = s; I[0] = k;
            } else {
                S[3] = S[2]; I[3] = I[2]; S[2] = S[1]; I[2] = I[1];
                S[1] = s; I[1] = k;
            }
        } else {
            if (s > S[2]) { S[3] = S[2]; I[3] = I[2]; S[2] = s; I[2] = k; }
            else          { S[3] = s; I[3] = k; }
        }
    }
}

// ---------------- prepass kernels ----------------
// per-row int8 quantize of x; one warp per row
__global__ void prep_x8(const float* __restrict__ x) {
    const int t = threadIdx.x, l = t & 31;
    const int row = blockIdx.x * 8 + (t >> 5);
    const float4* xr = (const float4*)(x + (size_t)row * DIM);
    float4 v1 = __ldg(&xr[l]), v2 = __ldg(&xr[l + 32]);
    float mx = fmaxf(fmaxf(fabsf(v1.x), fabsf(v1.y)), fmaxf(fabsf(v1.z), fabsf(v1.w)));
    mx = fmaxf(mx, fmaxf(fmaxf(fabsf(v2.x), fabsf(v2.y)), fmaxf(fabsf(v2.z), fabsf(v2.w))));
#pragma unroll
    for (int o = 16; o > 0; o >>= 1) mx = fmaxf(mx, __shfl_xor_sync(0xffffffffu, mx, o));
    mx = fmaxf(mx, 1e-20f);
    const float inv = 127.f / mx;
    unsigned* dst = (unsigned*)(g_Ai + (size_t)row * DIM);
    {
        int q0 = __float2int_rn(v1.x * inv), q1 = __float2int_rn(v1.y * inv);
        int q2 = __float2int_rn(v1.z * inv), q3 = __float2int_rn(v1.w * inv);
        dst[l] = (q0 & 0xff) | ((q1 & 0xff) << 8) | ((q2 & 0xff) << 16) | ((q3 & 0xff) << 24);
        q0 = __float2int_rn(v2.x * inv); q1 = __float2int_rn(v2.y * inv);
        q2 = __float2int_rn(v2.z * inv); q3 = __float2int_rn(v2.w * inv);
        dst[l + 32] = (q0 & 0xff) | ((q1 & 0xff) << 8) | ((q2 & 0xff) << 16) | ((q3 & 0xff) << 24);
    }
    if (l == 0) g_sx[row] = mx * (1.f / 127.f);
}

// per-code esq + max + scale
__global__ void se_esq_kernel(const float* __restrict__ emb) {
    int k = blockIdx.x * 256 + threadIdx.x;
    float s = 0.f, mx = 0.f;
#pragma unroll 8
    for (int d = 0; d < DIM; ++d) {
        float v = __ldg(&emb[(size_t)d * KCODES + k]);
        s = fmaf(v, v, s);
        mx = fmaxf(mx, fabsf(v));
    }
    mx = fmaxf(mx, 1e-20f);
    g_esq[k] = s;
    g_se[k] = 127.f / mx;
    g_ce[k] = make_float2(mx * (1.f / 127.f), s);
}

// transpose emb [D][K] -> ET fp32 [K][D] and int8 g_Bi [K][D]
__global__ void trans8(const float* __restrict__ emb) {
    __shared__ float tile[32][33];
    const int tx = threadIdx.x & 31, ty = threadIdx.x >> 5;
    const int k0 = blockIdx.x * 32, d0 = blockIdx.y * 32;
#pragma unroll
    for (int i = 0; i < 4; ++i)
        tile[ty + 8 * i][tx] = emb[(size_t)(d0 + ty + 8 * i) * KCODES + k0 + tx];
    __syncthreads();
#pragma unroll
    for (int i = 0; i < 4; ++i) {
        int kl = ty + 8 * i;
        float v = tile[tx][kl];
        float se = __ldg(&g_se[k0 + kl]);
        size_t o = (size_t)(k0 + kl) * DIM + d0 + tx;
        g_ET[o] = v;
        g_Bi[o] = (char)__float2int_rn(v * se);
    }
}

// ---------------- main kernel ----------------
__device__ __forceinline__ void issueB(uint32_t sb, int t, int c, int buf) {
    const int r = t >> 2, s4 = (t & 3) * 4;
    const char* src = g_Bi + ((size_t)(c * 64 + r)) * 256 + s4 * 16;
    uint32_t dst = sb + SOFF_B + buf * BUFSZ + r * PB + s4 * 16;
#pragma unroll
    for (int i = 0; i < 4; ++i) cpa16(dst + i * 16, src + i * 16);
    if (t < 32)
        cpa16(sb + SOFF_CE + buf * 512 + t * 16, (const char*)g_ce + c * 512 + t * 16);
}

__global__ void __launch_bounds__(256, 2)
vq_imma(const float* __restrict__ x, const float* __restrict__ emb,
        float* __restrict__ out) {
    extern __shared__ char sm[];
    const uint32_t sb = s2u(sm);
    const int t = threadIdx.x, l = t & 31, w = t >> 5;   // 8 warps
    const int g = w >> 1, h = w & 1;                     // row-group 0..3 (16 rows), code-half
    const int g0 = blockIdx.x * M_CTA;

    // ---- stage A tile (64 rows x 256 int8) ----
    {
        const char* asrc = g_Ai + (size_t)g0 * 256;
#pragma unroll
        for (int i = 0; i < 4; ++i) {
            int q = t + 256 * i, r = q >> 4, o = q & 15;
            cpa16(sb + SOFF_A + r * PB + o * 16, asrc + (size_t)r * 256 + o * 16);
        }
        cpcommit();
    }
#pragma unroll
    for (int p = 0; p < 3; ++p) { issueB(sb, t, p, p); cpcommit(); }

    cpwait<3>();
    __syncthreads();

    // ---- A fragments: 16 rows per warp, 8 ksteps ----
    unsigned aF[8][4];
    {
        const uint32_t laneA = (uint32_t)((l & 7) + ((l >> 3) & 1) * 8) * PB + ((l >> 4) & 1) * 16;
        uint32_t ab = sb + SOFF_A + g * 16 * PB + laneA;
#pragma unroll
        for (int ks = 0; ks < 8; ++ks)
            ldsm4(aF[ks][0], aF[ks][1], aF[ks][2], aF[ks][3], ab + ks * 32);
    }

    int acc[4][4];
#pragma unroll
    for (int n = 0; n < 4; ++n)
#pragma unroll
        for (int j = 0; j < 4; ++j) acc[n][j] = 0;

    float S[2][4];
    int   I[2][4];
#pragma unroll
    for (int u = 0; u < 2; ++u)
#pragma unroll
        for (int j = 0; j < 4; ++j) { S[u][j] = -FLT_MAX; I[u][j] = 0; }

    float tx2[2];
    {
        int r0 = g0 + g * 16 + (l >> 2);
        tx2[0] = 2.f * __ldg(&g_sx[r0]);
        tx2[1] = 2.f * __ldg(&g_sx[r0 + 8]);
    }

    // B ldsm lane constant: covers n-tiles (2p, 2p+1) of this warp's 32-code half
    const uint32_t laneB = (uint32_t)(h * 32 + ((l >> 4) & 1) * 8 + (l & 7)) * PB
                         + ((l >> 3) & 1) * 16;
    const int q2 = (l & 3) * 2;

    // ---- stream 128 chunks of 64 codes ----
#pragma unroll 1
    for (int c = 0; c < 128; ++c) {
        const int buf = c % 3;
        cpwait<2>();
        __syncthreads();
        const uint32_t bb = sb + SOFF_B + buf * BUFSZ + laneB;
#pragma unroll
        for (int ks = 0; ks < 8; ++ks) {
            unsigned b[4][2];
#pragma unroll
            for (int p = 0; p < 2; ++p)
                ldsm4(b[2 * p][0], b[2 * p][1], b[2 * p + 1][0], b[2 * p + 1][1],
                      bb + p * (16 * PB) + ks * 32);
#pragma unroll
            for (int n = 0; n < 4; ++n)
                mma_s8(acc[n], aF[ks], b[n][0], b[n][1]);
        }
        // per-chunk score epilogue
        const float2* ceS = (const float2*)(sm + SOFF_CE + buf * 512);
        const int cb = c * 64 + h * 32 + q2;
#pragma unroll
        for (int n = 0; n < 4; ++n) {
            float2 c0 = ceS[h * 32 + n * 8 + q2];
            float2 c1 = ceS[h * 32 + n * 8 + q2 + 1];
            const int k0 = cb + n * 8;
            top4(fmaf((float)acc[n][0], tx2[0] * c0.x, -c0.y), k0,     S[0], I[0]);
            top4(fmaf((float)acc[n][1], tx2[0] * c1.x, -c1.y), k0 + 1, S[0], I[0]);
            top4(fmaf((float)acc[n][2], tx2[1] * c0.x, -c0.y), k0,     S[1], I[1]);
            top4(fmaf((float)acc[n][3], tx2[1] * c1.x, -c1.y), k0 + 1, S[1], I[1]);
            acc[n][0] = 0; acc[n][1] = 0; acc[n][2] = 0; acc[n][3] = 0;
        }
        __syncthreads();
        if (c + 3 < 128) issueB(sb, t, c + 3, buf);
        cpcommit();
    }
    cpwait<0>();

    // ---- dump candidates: 32 per row ----
    int*   cand = (int*)sm;                 // 64*32*4 = 8 KB
    float* sco  = (float*)(sm + 8192);      // 8 KB
    int*   sIdx = (int*)(sm + 16384);       // 64 ints
    {
        const int rA = g * 16 + (l >> 2), rB = rA + 8;
        const int s0 = h * 16 + (l & 3) * 4;
#pragma unroll
        for (int j = 0; j < 4; ++j) {
            cand[rA * 32 + s0 + j] = I[0][j];
            sco [rA * 32 + s0 + j] = S[0][j];
            cand[rB * 32 + s0 + j] = I[1][j];
            sco [rB * 32 + s0 + j] = S[1][j];
        }
    }
    __syncthreads();

    // ---- selection: margin filter + exact sequential-d fp32 rescore ----
    if (t < M_CTA) {
        float m = -FLT_MAX;
#pragma unroll
        for (int s = 0; s < 32; ++s) m = fmaxf(m, sco[t * 32 + s]);
        const float thr = m - MARGIN;
        const float4* xr = (const float4*)(x + (size_t)(g0 + t) * DIM);
        float bs = -FLT_MAX; int bk = 0x7fffffff;
#pragma unroll 1
        for (int s = 0; s < 32; ++s) {
            if (sco[t * 32 + s] < thr) continue;
            const int kc = cand[t * 32 + s];
            const float4* er = (const float4*)(g_ET + (size_t)kc * DIM);
            float dot = 0.f;                      // strictly sequential over d
#pragma unroll 8
            for (int ii = 0; ii < 64; ++ii) {
                float4 a = __ldg(&xr[ii]);
                float4 b = __ldg(&er[ii]);
                dot = fmaf(a.x, b.x, dot);
                dot = fmaf(a.y, b.y, dot);
                dot = fmaf(a.z, b.z, dot);
                dot = fmaf(a.w, b.w, dot);
            }
            float sc = fmaf(2.f, dot, -__ldg(&g_esq[kc]));
            if (sc > bs || (sc == bs && kc < bk)) { bs = sc; bk = kc; }
        }
        sIdx[t] = bk;
        out[IDX_OFF + g0 + t] = (float)bk;
        atomicAdd(&g_counts[bk], 1.0f);
    }
    __syncthreads();

    // ---- fused quantize / loss / dw (256 threads: d = t, 64 rows) ----
    float lsum = 0.f;
    {
        const float* xg = x + (size_t)g0 * DIM + t;
        float* qg = out + (size_t)g0 * DIM + t;
        const float* ecol = emb + (size_t)t * KCODES;
        float* dwcol = g_dw + (size_t)t * KCODES;
#pragma unroll 4
        for (int j = 0; j < M_CTA; ++j) {
            const int bi = sIdx[j];
            float xv = xg[(size_t)j * DIM];
            float qv = __ldg(&ecol[bi]);
            float df = qv - xv;
            qg[(size_t)j * DIM] = xv + df;
            lsum += df * df;
            atomicAdd(&dwcol[bi], xv);
        }
    }
#pragma unroll
    for (int o = 16; o > 0; o >>= 1) lsum += __shfl_xor_sync(0xffffffffu, lsum, o);
    if (l == 0) atomicAdd(&g_loss, lsum);
}

// ---------------- finalize ----------------
__global__ void finalize_kernel(const float* __restrict__ ema_cs,
                                const int* __restrict__ counter,
                                float* __restrict__ out) {
    __shared__ float s_avg[KCODES];
    __shared__ float wn[8], wp[8], s_n;
    const int tid = threadIdx.x;
    const float debias = (float)(1.0 - pow(0.99, (double)(*counter + 1)));
    float nsum = 0.f, psum = 0.f;
    for (int i = tid; i < KCODES; i += 256) {
        float cnt = g_counts[i];
        float avg = (ema_cs[i] * DECAYF + cnt * OMD) / debias;
        s_avg[i] = avg; nsum += avg;
        float p = cnt * (1.0f / 16384.0f);
        psum += p * logf(p + 1e-10f);
    }
#pragma unroll
    for (int o = 16; o > 0; o >>= 1) {
        nsum += __shfl_xor_sync(0xffffffffu, nsum, o);
        psum += __shfl_xor_sync(0xffffffffu, psum, o);
    }
    if ((tid & 31) == 0) { wn[tid >> 5] = nsum; wp[tid >> 5] = psum; }
    __syncthreads();
    if (tid == 0) {
        float n = 0.f, ps = 0.f;
#pragma unroll
        for (int w = 0; w < 8; ++w) { n += wn[w]; ps += wp[w]; }
        s_n = n;
        out[LOSS_OFF] = 0.25f * (g_loss / 4194304.0f);
        out[PERP_OFF] = expf(-ps);
    }
    __syncthreads();
    const float n = s_n, denom = n + KEPS;
    for (int i = tid; i < KCODES; i += 256)
        g_scale[i] = 1.0f / (debias * (((s_avg[i] + 1e-5f) / denom) * n));
}

// ---------------- new_embeddings ----------------
__global__ void emb_out_kernel(const float* __restrict__ ema_dw,
                               const float* __restrict__ emb,
                               const int* __restrict__ istrain,
                               float* __restrict__ out_emb) {
    const int i = blockIdx.x * 256 + threadIdx.x;
    out_emb[i] = (*istrain)
        ? (ema_dw[i] * DECAYF + g_dw[i] * OMD) * g_scale[i & (KCODES - 1)]
        : emb[i];
}

// ---------------- host launch ----------------
extern "C" void kernel_launch(void* const* d_in, const int* in_sizes, int n_in,
                              void* d_out, int out_size) {
    const float* x       = (const float*)d_in[0];
    const float* emb     = (const float*)d_in[1];
    const float* ema_cs  = (const float*)d_in[2];
    const float* ema_dw  = (const float*)d_in[3];
    const int*   counter = (const int*)d_in[4];
    const int*   istrain = (const int*)d_in[5];
    float* out = (float*)d_out;

    void *p_dw, *p_cnt, *p_loss;
    cudaGetSymbolAddress(&p_dw, g_dw);
    cudaGetSymbolAddress(&p_cnt, g_counts);
    cudaGetSymbolAddress(&p_loss, g_loss);
    cudaMemsetAsync(p_dw, 0, sizeof(float) * DIM * KCODES, 0);
    cudaMemsetAsync(p_cnt, 0, sizeof(float) * KCODES, 0);
    cudaMemsetAsync(p_loss, 0, sizeof(float), 0);

    cudaFuncSetAttribute(vq_imma, cudaFuncAttributeMaxDynamicSharedMemorySize, SMEM_MAIN);

    prep_x8<<<NROWS / 8, 256>>>(x);
    se_esq_kernel<<<KCODES / 256, 256>>>(emb);
    trans8<<<dim3(KCODES / 32, DIM / 32), 256>>>(emb);
    vq_imma<<<NROWS / M_CTA, 256, SMEM_MAIN>>>(x, emb, out);
    finalize_kernel<<<1, 256>>>(ema_cs, counter, out);
    emb_out_kernel<<<(DIM * KCODES) / 256, 256>>>(ema_dw, emb, istrain, out + EMB_OFF);
}

// round 11
// speedup vs baseline: 1.5042x; 1.5042x over previous
#include <cuda_runtime.h>
#include <cuda_bf16.h>
#include <cstdint>
#include <math.h>
#include <float.h>

#define KCODES 8192
#define DIM    256
#define NROWS  16384

#define Q_OFF     0
#define LOSS_OFF  4194304
#define PERP_OFF  4194305
#define IDX_OFF   4194306
#define EMB_OFF   4210690

#define DECAYF 0.99f
#define OMD    ((float)(1.0 - 0.99))
#define KEPS   ((float)(8192.0 * 1e-5))
#define MARGIN 0.6f

// main-kernel smem geometry (fp8 tiles, 272B padded rows -> conflict-free ldmatrix)
#define PB      272
#define M_CTA   64
#define SOFF_A  0                       // 64*272 = 17408
#define SOFF_B  17408                   // 3 bufs * 17408
#define BUFSZ   17408
#define SOFF_CE 69632                   // 3 * 512 (float2 per code: {se, esq})
#define SMEM_MAIN 71168

// ---------------- device scratch ----------------
__device__ __align__(16) char  g_Ai[(size_t)NROWS * DIM];     // 4 MB e4m3 rows
__device__ __align__(16) char  g_Bi[(size_t)KCODES * DIM];    // 2 MB e4m3 code-major
__device__ __align__(16) float g_ET[(size_t)KCODES * DIM];    // 8 MB fp32 code-major (exact rescore)
__device__ float g_sx[NROWS];                                  // per-row x dequant scale (max/448)
__device__ float g_se[KCODES];                                 // per-code quant scale (448/max)
__device__ __align__(16) float2 g_ce[KCODES];                  // {max/448, esq}
__device__ float g_esq[KCODES];
__device__ float g_dw[DIM * KCODES];
__device__ float g_counts[KCODES];
__device__ float g_scale[KCODES];
__device__ float g_loss;

// ---------------- PTX helpers (baseline compute_103 only) ----------------
__device__ __forceinline__ uint32_t s2u(const void* p) {
    uint32_t a;
    asm("{ .reg .u64 t; cvta.to.shared.u64 t, %1; cvt.u32.u64 %0, t; }" : "=r"(a) : "l"(p));
    return a;
}
__device__ __forceinline__ void cpa16(uint32_t dst, const void* src) {
    asm volatile("cp.async.cg.shared.global [%0], [%1], 16;" :: "r"(dst), "l"(src) : "memory");
}
__device__ __forceinline__ void cpcommit() {
    asm volatile("cp.async.commit_group;" ::: "memory");
}
template <int N> __device__ __forceinline__ void cpwait() {
    asm volatile("cp.async.wait_group %0;" :: "n"(N) : "memory");
}
__device__ __forceinline__ void ldsm4(unsigned& r0, unsigned& r1, unsigned& r2, unsigned& r3,
                                      uint32_t a) {
    asm volatile("ldmatrix.sync.aligned.m8n8.x4.shared.b16 {%0,%1,%2,%3},[%4];"
                 : "=r"(r0), "=r"(r1), "=r"(r2), "=r"(r3) : "r"(a));
}
__device__ __forceinline__ void mma_fp8(float (&d)[4], const unsigned (&a)[4],
                                        const unsigned b0, const unsigned b1) {
    asm volatile("mma.sync.aligned.m16n8k32.row.col.f32.e4m3.e4m3.f32 "
                 "{%0,%1,%2,%3},{%4,%5,%6,%7},{%8,%9},{%0,%1,%2,%3};"
                 : "+f"(d[0]), "+f"(d[1]), "+f"(d[2]), "+f"(d[3])
                 : "r"(a[0]), "r"(a[1]), "r"(a[2]), "r"(a[3]), "r"(b0), "r"(b1));
}
// pack 4 floats -> 4 e4m3 bytes (a = lowest byte)
__device__ __forceinline__ unsigned pack_e4m3x4(float a, float b, float c, float d) {
    unsigned short lo, hi;
    asm("cvt.rn.satfinite.e4m3x2.f32 %0, %1, %2;" : "=h"(lo) : "f"(b), "f"(a));
    asm("cvt.rn.satfinite.e4m3x2.f32 %0, %1, %2;" : "=h"(hi) : "f"(d), "f"(c));
    return (unsigned)lo | ((unsigned)hi << 16);
}
__device__ __forceinline__ char f2e4m3(float v) {
    unsigned short us;
    asm("cvt.rn.satfinite.e4m3x2.f32 %0, %1, %2;" : "=h"(us) : "f"(0.f), "f"(v));
    return (char)(us & 0xff);
}
__device__ __forceinline__ void top4(float s, int k, float (&S)[4], int (&I)[4]) {
    if (s > S[3]) {
        if (s > S[1]) {
            if (s > S[0]) {
                S[3] = S[2]; I[3] = I[2]; S[2] = S[1]; I[2] = I[1];
                S[1] = S[0]; I[1] = I[0]; S[0] = s; I[0] = k;
            } else {
                S[3] = S[2]; I[3] = I[2]; S[2] = S[1]; I[2] = I[1];
                S[1] = s; I[1] = k;
            }
        } else {
            if (s > S[2]) { S[3] = S[2]; I[3] = I[2]; S[2] = s; I[2] = k; }
            else          { S[3] = s; I[3] = k; }
        }
    }
}

// ---------------- prepass kernels ----------------
// per-row e4m3 quantize of x; one warp per row
__global__ void prep_x8(const float* __restrict__ x) {
    const int t = threadIdx.x, l = t & 31;
    const int row = blockIdx.x * 8 + (t >> 5);
    const float4* xr = (const float4*)(x + (size_t)row * DIM);
    float4 v1 = __ldg(&xr[l]), v2 = __ldg(&xr[l + 32]);
    float mx = fmaxf(fmaxf(fabsf(v1.x), fabsf(v1.y)), fmaxf(fabsf(v1.z), fabsf(v1.w)));
    mx = fmaxf(mx, fmaxf(fmaxf(fabsf(v2.x), fabsf(v2.y)), fmaxf(fabsf(v2.z), fabsf(v2.w))));
#pragma unroll
    for (int o = 16; o > 0; o >>= 1) mx = fmaxf(mx, __shfl_xor_sync(0xffffffffu, mx, o));
    mx = fmaxf(mx, 1e-20f);
    const float inv = 448.f / mx;
    unsigned* dst = (unsigned*)(g_Ai + (size_t)row * DIM);
    dst[l]      = pack_e4m3x4(v1.x * inv, v1.y * inv, v1.z * inv, v1.w * inv);
    dst[l + 32] = pack_e4m3x4(v2.x * inv, v2.y * inv, v2.z * inv, v2.w * inv);
    if (l == 0) g_sx[row] = mx * (1.f / 448.f);
}

// per-code esq + max + scale
__global__ void se_esq_kernel(const float* __restrict__ emb) {
    int k = blockIdx.x * 256 + threadIdx.x;
    float s = 0.f, mx = 0.f;
#pragma unroll 8
    for (int d = 0; d < DIM; ++d) {
        float v = __ldg(&emb[(size_t)d * KCODES + k]);
        s = fmaf(v, v, s);
        mx = fmaxf(mx, fabsf(v));
    }
    mx = fmaxf(mx, 1e-20f);
    g_esq[k] = s;
    g_se[k] = 448.f / mx;
    g_ce[k] = make_float2(mx * (1.f / 448.f), s);
}

// transpose emb [D][K] -> ET fp32 [K][D] and e4m3 g_Bi [K][D]
__global__ void trans8(const float* __restrict__ emb) {
    __shared__ float tile[32][33];
    const int tx = threadIdx.x & 31, ty = threadIdx.x >> 5;
    const int k0 = blockIdx.x * 32, d0 = blockIdx.y * 32;
#pragma unroll
    for (int i = 0; i < 4; ++i)
        tile[ty + 8 * i][tx] = emb[(size_t)(d0 + ty + 8 * i) * KCODES + k0 + tx];
    __syncthreads();
#pragma unroll
    for (int i = 0; i < 4; ++i) {
        int kl = ty + 8 * i;
        float v = tile[tx][kl];
        float se = __ldg(&g_se[k0 + kl]);
        size_t o = (size_t)(k0 + kl) * DIM + d0 + tx;
        g_ET[o] = v;
        g_Bi[o] = f2e4m3(v * se);
    }
}

// ---------------- main kernel ----------------
__device__ __forceinline__ void issueB(uint32_t sb, int t, int c, int buf) {
    const int r = t >> 2, s4 = (t & 3) * 4;
    const char* src = g_Bi + ((size_t)(c * 64 + r)) * 256 + s4 * 16;
    uint32_t dst = sb + SOFF_B + buf * BUFSZ + r * PB + s4 * 16;
#pragma unroll
    for (int i = 0; i < 4; ++i) cpa16(dst + i * 16, src + i * 16);
    if (t < 32)
        cpa16(sb + SOFF_CE + buf * 512 + t * 16, (const char*)g_ce + c * 512 + t * 16);
}

__global__ void __launch_bounds__(256, 2)
vq_fp8(const float* __restrict__ x, const float* __restrict__ emb,
       float* __restrict__ out) {
    extern __shared__ char sm[];
    const uint32_t sb = s2u(sm);
    const int t = threadIdx.x, l = t & 31, w = t >> 5;   // 8 warps
    const int g = w >> 1, h = w & 1;                     // row-group 0..3 (16 rows), code-half
    const int g0 = blockIdx.x * M_CTA;

    // ---- stage A tile (64 rows x 256 e4m3) ----
    {
        const char* asrc = g_Ai + (size_t)g0 * 256;
#pragma unroll
        for (int i = 0; i < 4; ++i) {
            int q = t + 256 * i, r = q >> 4, o = q & 15;
            cpa16(sb + SOFF_A + r * PB + o * 16, asrc + (size_t)r * 256 + o * 16);
        }
        cpcommit();
    }
#pragma unroll
    for (int p = 0; p < 3; ++p) { issueB(sb, t, p, p); cpcommit(); }

    cpwait<3>();
    __syncthreads();

    // ---- A fragments: 16 rows per warp, 8 ksteps ----
    unsigned aF[8][4];
    {
        const uint32_t laneA = (uint32_t)((l & 7) + ((l >> 3) & 1) * 8) * PB + ((l >> 4) & 1) * 16;
        uint32_t ab = sb + SOFF_A + g * 16 * PB + laneA;
#pragma unroll
        for (int ks = 0; ks < 8; ++ks)
            ldsm4(aF[ks][0], aF[ks][1], aF[ks][2], aF[ks][3], ab + ks * 32);
    }

    float acc[4][4];
#pragma unroll
    for (int n = 0; n < 4; ++n)
#pragma unroll
        for (int j = 0; j < 4; ++j) acc[n][j] = 0.f;

    float S[2][4];
    int   I[2][4];
#pragma unroll
    for (int u = 0; u < 2; ++u)
#pragma unroll
        for (int j = 0; j < 4; ++j) { S[u][j] = -FLT_MAX; I[u][j] = 0; }

    float tx2[2];
    {
        int r0 = g0 + g * 16 + (l >> 2);
        tx2[0] = 2.f * __ldg(&g_sx[r0]);
        tx2[1] = 2.f * __ldg(&g_sx[r0 + 8]);
    }

    // B ldsm lane constant: covers n-tiles (2p, 2p+1) of this warp's 32-code half
    const uint32_t laneB = (uint32_t)(h * 32 + ((l >> 4) & 1) * 8 + (l & 7)) * PB
                         + ((l >> 3) & 1) * 16;
    const int q2 = (l & 3) * 2;

    // ---- stream 128 chunks of 64 codes ----
#pragma unroll 1
    for (int c = 0; c < 128; ++c) {
        const int buf = c % 3;
        cpwait<2>();
        __syncthreads();
        const uint32_t bb = sb + SOFF_B + buf * BUFSZ + laneB;
#pragma unroll
        for (int ks = 0; ks < 8; ++ks) {
            unsigned b[4][2];
#pragma unroll
            for (int p = 0; p < 2; ++p)
                ldsm4(b[2 * p][0], b[2 * p][1], b[2 * p + 1][0], b[2 * p + 1][1],
                      bb + p * (16 * PB) + ks * 32);
#pragma unroll
            for (int n = 0; n < 4; ++n)
                mma_fp8(acc[n], aF[ks], b[n][0], b[n][1]);
        }
        // per-chunk score epilogue
        const float2* ceS = (const float2*)(sm + SOFF_CE + buf * 512);
        const int cb = c * 64 + h * 32 + q2;
#pragma unroll
        for (int n = 0; n < 4; ++n) {
            float2 c0 = ceS[h * 32 + n * 8 + q2];
            float2 c1 = ceS[h * 32 + n * 8 + q2 + 1];
            const int k0 = cb + n * 8;
            top4(fmaf(acc[n][0], tx2[0] * c0.x, -c0.y), k0,     S[0], I[0]);
            top4(fmaf(acc[n][1], tx2[0] * c1.x, -c1.y), k0 + 1, S[0], I[0]);
            top4(fmaf(acc[n][2], tx2[1] * c0.x, -c0.y), k0,     S[1], I[1]);
            top4(fmaf(acc[n][3], tx2[1] * c1.x, -c1.y), k0 + 1, S[1], I[1]);
            acc[n][0] = 0.f; acc[n][1] = 0.f; acc[n][2] = 0.f; acc[n][3] = 0.f;
        }
        __syncthreads();
        if (c + 3 < 128) issueB(sb, t, c + 3, buf);
        cpcommit();
    }
    cpwait<0>();

    // ---- dump candidates: 32 per row ----
    int*   cand = (int*)sm;                 // 64*32*4 = 8 KB
    float* sco  = (float*)(sm + 8192);      // 8 KB
    int*   sIdx = (int*)(sm + 16384);       // 64 ints
    {
        const int rA = g * 16 + (l >> 2), rB = rA + 8;
        const int s0 = h * 16 + (l & 3) * 4;
#pragma unroll
        for (int j = 0; j < 4; ++j) {
            cand[rA * 32 + s0 + j] = I[0][j];
            sco [rA * 32 + s0 + j] = S[0][j];
            cand[rB * 32 + s0 + j] = I[1][j];
            sco [rB * 32 + s0 + j] = S[1][j];
        }
    }
    __syncthreads();

    // ---- selection: margin filter + exact sequential-d fp32 rescore ----
    if (t < M_CTA) {
        float m = -FLT_MAX;
#pragma unroll
        for (int s = 0; s < 32; ++s) m = fmaxf(m, sco[t * 32 + s]);
        const float thr = m - MARGIN;
        const float4* xr = (const float4*)(x + (size_t)(g0 + t) * DIM);
        float bs = -FLT_MAX; int bk = 0x7fffffff;
#pragma unroll 1
        for (int s = 0; s < 32; ++s) {
            if (sco[t * 32 + s] < thr) continue;
            const int kc = cand[t * 32 + s];
            const float4* er = (const float4*)(g_ET + (size_t)kc * DIM);
            float dot = 0.f;                      // strictly sequential over d
#pragma unroll 8
            for (int ii = 0; ii < 64; ++ii) {
                float4 a = __ldg(&xr[ii]);
                float4 b = __ldg(&er[ii]);
                dot = fmaf(a.x, b.x, dot);
                dot = fmaf(a.y, b.y, dot);
                dot = fmaf(a.z, b.z, dot);
                dot = fmaf(a.w, b.w, dot);
            }
            float sc = fmaf(2.f, dot, -__ldg(&g_esq[kc]));
            if (sc > bs || (sc == bs && kc < bk)) { bs = sc; bk = kc; }
        }
        sIdx[t] = bk;
        out[IDX_OFF + g0 + t] = (float)bk;
        atomicAdd(&g_counts[bk], 1.0f);
    }
    __syncthreads();

    // ---- fused quantize / loss / dw (256 threads: d = t, 64 rows) ----
    float lsum = 0.f;
    {
        const float* xg = x + (size_t)g0 * DIM + t;
        float* qg = out + (size_t)g0 * DIM + t;
        const float* ecol = emb + (size_t)t * KCODES;
        float* dwcol = g_dw + (size_t)t * KCODES;
#pragma unroll 4
        for (int j = 0; j < M_CTA; ++j) {
            const int bi = sIdx[j];
            float xv = xg[(size_t)j * DIM];
            float qv = __ldg(&ecol[bi]);
            float df = qv - xv;
            qg[(size_t)j * DIM] = xv + df;
            lsum += df * df;
            atomicAdd(&dwcol[bi], xv);
        }
    }
#pragma unroll
    for (int o = 16; o > 0; o >>= 1) lsum += __shfl_xor_sync(0xffffffffu, lsum, o);
    if (l == 0) atomicAdd(&g_loss, lsum);
}

// ---------------- finalize ----------------
__global__ void finalize_kernel(const float* __restrict__ ema_cs,
                                const int* __restrict__ counter,
                                float* __restrict__ out) {
    __shared__ float s_avg[KCODES];
    __shared__ float wn[8], wp[8], s_n;
    const int tid = threadIdx.x;
    const float debias = (float)(1.0 - pow(0.99, (double)(*counter + 1)));
    float nsum = 0.f, psum = 0.f;
    for (int i = tid; i < KCODES; i += 256) {
        float cnt = g_counts[i];
        float avg = (ema_cs[i] * DECAYF + cnt * OMD) / debias;
        s_avg[i] = avg; nsum += avg;
        float p = cnt * (1.0f / 16384.0f);
        psum += p * logf(p + 1e-10f);
    }
#pragma unroll
    for (int o = 16; o > 0; o >>= 1) {
        nsum += __shfl_xor_sync(0xffffffffu, nsum, o);
        psum += __shfl_xor_sync(0xffffffffu, psum, o);
    }
    if ((tid & 31) == 0) { wn[tid >> 5] = nsum; wp[tid >> 5] = psum; }
    __syncthreads();
    if (tid == 0) {
        float n = 0.f, ps = 0.f;
#pragma unroll
        for (int w = 0; w < 8; ++w) { n += wn[w]; ps += wp[w]; }
        s_n = n;
        out[LOSS_OFF] = 0.25f * (g_loss / 4194304.0f);
        out[PERP_OFF] = expf(-ps);
    }
    __syncthreads();
    const float n = s_n, denom = n + KEPS;
    for (int i = tid; i < KCODES; i += 256)
        g_scale[i] = 1.0f / (debias * (((s_avg[i] + 1e-5f) / denom) * n));
}

// ---------------- new_embeddings ----------------
__global__ void emb_out_kernel(const float* __restrict__ ema_dw,
                               const float* __restrict__ emb,
                               const int* __restrict__ istrain,
                               float* __restrict__ out_emb) {
    const int i = blockIdx.x * 256 + threadIdx.x;
    out_emb[i] = (*istrain)
        ? (ema_dw[i] * DECAYF + g_dw[i] * OMD) * g_scale[i & (KCODES - 1)]
        : emb[i];
}

// ---------------- host launch ----------------
extern "C" void kernel_launch(void* const* d_in, const int* in_sizes, int n_in,
                              void* d_out, int out_size) {
    const float* x       = (const float*)d_in[0];
    const float* emb     = (const float*)d_in[1];
    const float* ema_cs  = (const float*)d_in[2];
    const float* ema_dw  = (const float*)d_in[3];
    const int*   counter = (const int*)d_in[4];
    const int*   istrain = (const int*)d_in[5];
    float* out = (float*)d_out;

    void *p_dw, *p_cnt, *p_loss;
    cudaGetSymbolAddress(&p_dw, g_dw);
    cudaGetSymbolAddress(&p_cnt, g_counts);
    cudaGetSymbolAddress(&p_loss, g_loss);
    cudaMemsetAsync(p_dw, 0, sizeof(float) * DIM * KCODES, 0);
    cudaMemsetAsync(p_cnt, 0, sizeof(float) * KCODES, 0);
    cudaMemsetAsync(p_loss, 0, sizeof(float), 0);

    cudaFuncSetAttribute(vq_fp8, cudaFuncAttributeMaxDynamicSharedMemorySize, SMEM_MAIN);

    prep_x8<<<NROWS / 8, 256>>>(x);
    se_esq_kernel<<<KCODES / 256, 256>>>(emb);
    trans8<<<dim3(KCODES / 32, DIM / 32), 256>>>(emb);
    vq_fp8<<<NROWS / M_CTA, 256, SMEM_MAIN>>>(x, emb, out);
    finalize_kernel<<<1, 256>>>(ema_cs, counter, out);
    emb_out_kernel<<<(DIM * KCODES) / 256, 256>>>(ema_dw, emb, istrain, out + EMB_OFF);
}

// round 13
// speedup vs baseline: 1.7860x; 1.1874x over previous
#include <cuda_runtime.h>
#include <cuda_bf16.h>
#include <cstdint>
#include <math.h>
#include <float.h>

#define KCODES 8192
#define DIM    256
#define NROWS  16384
#define NCTA   148
#define MWIN   112                      // rows computed per CTA (window)
#define NTHR   448                      // 14 warps

#define Q_OFF     0
#define LOSS_OFF  4194304
#define PERP_OFF  4194305
#define IDX_OFF   4194306
#define EMB_OFF   4210690

#define DECAYF 0.99f
#define OMD    ((float)(1.0 - 0.99))
#define KEPS   ((float)(8192.0 * 1e-5))
#define MARGIN 0.3f

// smem geometry (bf16 tiles, 560B padded rows -> conflict-free ldmatrix)
#define PB      560
#define BUFSZ   (64 * PB)               // 35840
#define SOFF_B  (MWIN * PB)             // 62720
#define SOFF_ESQ (SOFF_B + 3 * BUFSZ)   // 170240
#define SMEM_MAIN (SOFF_ESQ + 3 * 256)  // 171008

// ---------------- device scratch ----------------
__device__ __align__(16) __nv_bfloat16 g_Abf[(size_t)NROWS * DIM];   // 8 MB
__device__ __align__(16) __nv_bfloat16 g_Bc[(size_t)KCODES * DIM];   // 4 MB code-major
__device__ __align__(16) float g_ET[(size_t)KCODES * DIM];           // 8 MB fp32 code-major
__device__ float g_esq[KCODES];
__device__ float g_dw[DIM * KCODES];
__device__ float g_counts[KCODES];
__device__ float g_scale[KCODES];
__device__ float g_loss;

// ---------------- PTX helpers ----------------
__device__ __forceinline__ uint32_t s2u(const void* p) {
    uint32_t a;
    asm("{ .reg .u64 t; cvta.to.shared.u64 t, %1; cvt.u32.u64 %0, t; }" : "=r"(a) : "l"(p));
    return a;
}
__device__ __forceinline__ void cpa16(uint32_t dst, const void* src) {
    asm volatile("cp.async.cg.shared.global [%0], [%1], 16;" :: "r"(dst), "l"(src) : "memory");
}
__device__ __forceinline__ void cpcommit() {
    asm volatile("cp.async.commit_group;" ::: "memory");
}
template <int N> __device__ __forceinline__ void cpwait() {
    asm volatile("cp.async.wait_group %0;" :: "n"(N) : "memory");
}
__device__ __forceinline__ void ldsm4(unsigned& r0, unsigned& r1, unsigned& r2, unsigned& r3,
                                      uint32_t a) {
    asm volatile("ldmatrix.sync.aligned.m8n8.x4.shared.b16 {%0,%1,%2,%3},[%4];"
                 : "=r"(r0), "=r"(r1), "=r"(r2), "=r"(r3) : "r"(a));
}
__device__ __forceinline__ void mma_bf16(float (&d)[4], const unsigned (&a)[4],
                                         const unsigned b0, const unsigned b1) {
    asm volatile("mma.sync.aligned.m16n8k16.row.col.f32.bf16.bf16.f32 "
                 "{%0,%1,%2,%3},{%4,%5,%6,%7},{%8,%9},{%0,%1,%2,%3};"
                 : "+f"(d[0]), "+f"(d[1]), "+f"(d[2]), "+f"(d[3])
                 : "r"(a[0]), "r"(a[1]), "r"(a[2]), "r"(a[3]), "r"(b0), "r"(b1));
}
__device__ __forceinline__ void top4(float s, int k, float (&S)[4], int (&I)[4]) {
    if (s > S[3]) {
        if (s > S[1]) {
            if (s > S[0]) {
                S[3] = S[2]; I[3] = I[2]; S[2] = S[1]; I[2] = I[1];
                S[1] = S[0]; I[1] = I[0]; S[0] = s; I[0] = k;
            } else {
                S[3] = S[2]; I[3] = I[2]; S[2] = S[1]; I[2] = I[1];
                S[1] = s; I[1] = k;
            }
        } else {
            if (s > S[2]) { S[3] = S[2]; I[3] = I[2]; S[2] = s; I[2] = k; }
            else          { S[3] = s; I[3] = k; }
        }
    }
}

// ---------------- merged prepass kernel ----------------
// bid < 4096            : x -> bf16 (1 float4 per thread)
// 4096 <= bid < 6144    : transpose emb -> g_ET (fp32) + g_Bc (bf16), 32x32 tiles
// 6144 <= bid < 6176    : esq (deterministic column sums)
__global__ void prep_all(const float* __restrict__ x, const float* __restrict__ emb) {
    __shared__ float tile[32][33];
    const int bid = blockIdx.x, t = threadIdx.x;
    if (bid < 4096) {
        int i = bid * 256 + t;
        float4 v = ((const float4*)x)[i];
        __nv_bfloat162 lo = __floats2bfloat162_rn(v.x, v.y);
        __nv_bfloat162 hi = __floats2bfloat162_rn(v.z, v.w);
        uint2 pk;
        pk.x = *(unsigned*)&lo; pk.y = *(unsigned*)&hi;
        ((uint2*)g_Abf)[i] = pk;
    } else if (bid < 6144) {
        const int pe = bid - 4096;
        const int k0 = (pe >> 3) * 32, d0 = (pe & 7) * 32;
        const int tx = t & 31, ty = t >> 5;
#pragma unroll
        for (int i = 0; i < 4; ++i)
            tile[ty + 8 * i][tx] = emb[(size_t)(d0 + ty + 8 * i) * KCODES + k0 + tx];
        __syncthreads();
#pragma unroll
        for (int i = 0; i < 4; ++i) {
            int kl = ty + 8 * i;
            float v = tile[tx][kl];
            size_t o = (size_t)(k0 + kl) * DIM + d0 + tx;
            g_ET[o] = v;
            g_Bc[o] = __float2bfloat16(v);
        }
    } else {
        int k = (bid - 6144) * 256 + t;
        float s = 0.f;
#pragma unroll 8
        for (int d = 0; d < DIM; ++d) {
            float v = __ldg(&emb[(size_t)d * KCODES + k]);
            s = fmaf(v, v, s);
        }
        g_esq[k] = s;
    }
}

// ---------------- main kernel ----------------
__device__ __forceinline__ void issueB(uint32_t sb, int t, int c, int buf) {
    const char* src = (const char*)g_Bc + (size_t)c * 64 * 512;
    const uint32_t dst = sb + SOFF_B + buf * BUFSZ;
#pragma unroll
    for (int i = 0; i < 5; ++i) {          // ceil(2048/448) = 5  (R12 bug: was 4)
        int q = t + NTHR * i;               // 2048 16B transfers total
        if (q < 2048) {
            int r = q >> 5, o = q & 31;
            cpa16(dst + r * PB + o * 16, src + (size_t)r * 512 + o * 16);
        }
    }
    if (t < 16)
        cpa16(sb + SOFF_ESQ + buf * 256 + t * 16, (const char*)g_esq + c * 256 + t * 16);
}

__global__ void __launch_bounds__(NTHR, 1)
vq_hmma(const float* __restrict__ x, const float* __restrict__ emb,
        float* __restrict__ out) {
    extern __shared__ char sm[];
    const uint32_t sb = s2u(sm);
    const int t = threadIdx.x, l = t & 31, w = t >> 5;   // 14 warps
    const int g = w >> 1, h = w & 1;                     // row-group 0..6, code-half
    const int bid = blockIdx.x;
    const int o0 = (int)(((long long)bid * NROWS) / NCTA);
    const int o1 = (int)(((long long)(bid + 1) * NROWS) / NCTA);
    const int w0 = (o0 > NROWS - MWIN) ? (NROWS - MWIN) : o0;
    const int nown = o1 - o0;

    // ---- stage A window (112 rows x 256 bf16) ----
    {
        const char* asrc = (const char*)g_Abf + (size_t)w0 * 512;
#pragma unroll
        for (int i = 0; i < 8; ++i) {
            int q = t + NTHR * i;            // 3584 16B transfers
            if (q < 3584) {
                int r = q >> 5, o = q & 31;
                cpa16(sb + r * PB + o * 16, asrc + (size_t)r * 512 + o * 16);
            }
        }
        cpcommit();
    }
#pragma unroll
    for (int p = 0; p < 3; ++p) { issueB(sb, t, p, p); cpcommit(); }

    cpwait<3>();
    __syncthreads();

    // ---- A fragments: 16 rows per warp ----
    unsigned aF[16][4];
    {
        uint32_t ab = sb + (g * 16 + (l & 15)) * PB + (l >> 4) * 16;
#pragma unroll
        for (int kt = 0; kt < 16; ++kt)
            ldsm4(aF[kt][0], aF[kt][1], aF[kt][2], aF[kt][3], ab + kt * 32);
    }

    float acc[4][4];
#pragma unroll
    for (int n = 0; n < 4; ++n)
#pragma unroll
        for (int j = 0; j < 4; ++j) acc[n][j] = 0.f;

    float Sa[4], Sb2[4];
    int   Ia[4], Ib[4];
#pragma unroll
    for (int j = 0; j < 4; ++j) {
        Sa[j] = -FLT_MAX; Sb2[j] = -FLT_MAX; Ia[j] = 0; Ib[j] = 0;
    }

    const uint32_t laneB = (uint32_t)(h * 32 + (l & 7) + ((l >> 4) << 3)) * PB
                         + ((l >> 3) & 1) * 16;
    const int q2 = (l & 3) * 2;

    // ---- stream 128 chunks of 64 codes ----
#pragma unroll 1
    for (int c = 0; c < 128; ++c) {
        const int buf = c % 3;
        cpwait<2>();
        __syncthreads();
        const uint32_t bb = sb + SOFF_B + buf * BUFSZ + laneB;
#pragma unroll
        for (int kt = 0; kt < 16; ++kt) {
            unsigned b[4][2];
#pragma unroll
            for (int p = 0; p < 2; ++p)
                ldsm4(b[2 * p][0], b[2 * p][1], b[2 * p + 1][0], b[2 * p + 1][1],
                      bb + p * (16 * PB) + kt * 32);
#pragma unroll
            for (int n = 0; n < 4; ++n)
                mma_bf16(acc[n], aF[kt], b[n][0], b[n][1]);
        }
        const float* eSq = (const float*)(sm + SOFF_ESQ + buf * 256);
        const int cb = c * 64 + h * 32 + q2;
#pragma unroll
        for (int n = 0; n < 4; ++n) {
            float2 ev = *(const float2*)&eSq[h * 32 + n * 8 + q2];
            const int k0 = cb + n * 8;
            top4(fmaf(2.f, acc[n][0], -ev.x), k0,     Sa,  Ia);
            top4(fmaf(2.f, acc[n][1], -ev.y), k0 + 1, Sa,  Ia);
            top4(fmaf(2.f, acc[n][2], -ev.x), k0,     Sb2, Ib);
            top4(fmaf(2.f, acc[n][3], -ev.y), k0 + 1, Sb2, Ib);
            acc[n][0] = 0.f; acc[n][1] = 0.f; acc[n][2] = 0.f; acc[n][3] = 0.f;
        }
        __syncthreads();
        if (c + 3 < 128) issueB(sb, t, c + 3, buf);
        cpcommit();
    }
    cpwait<0>();

    // ---- dump candidates: 32 per window row ----
    int*   cand = (int*)sm;                 // 112*32*4 = 14336
    float* sco  = (float*)(sm + 14336);     // 14336
    int*   sIdx = (int*)(sm + 28672);       // 112 ints
    {
        const int rA = g * 16 + (l >> 2), rB = rA + 8;
        const int s0 = h * 16 + (l & 3) * 4;
#pragma unroll
        for (int j = 0; j < 4; ++j) {
            cand[rA * 32 + s0 + j] = Ia[j];
            sco [rA * 32 + s0 + j] = Sa[j];
            cand[rB * 32 + s0 + j] = Ib[j];
            sco [rB * 32 + s0 + j] = Sb2[j];
        }
    }
    __syncthreads();

    // ---- selection on OWNED rows: margin filter + exact sequential-d rescore ----
    if (t < nown) {
        const int wr = (o0 - w0) + t;       // window-relative row
        float m = -FLT_MAX;
#pragma unroll
        for (int s = 0; s < 32; ++s) m = fmaxf(m, sco[wr * 32 + s]);
        const float thr = m - MARGIN;
        const float4* xr = (const float4*)(x + (size_t)(o0 + t) * DIM);
        float bs = -FLT_MAX; int bk = 0x7fffffff;
#pragma unroll 1
        for (int s = 0; s < 32; ++s) {
            if (sco[wr * 32 + s] < thr) continue;
            const int kc = cand[wr * 32 + s];
            const float4* er = (const float4*)(g_ET + (size_t)kc * DIM);
            float dot = 0.f;
#pragma unroll 8
            for (int ii = 0; ii < 64; ++ii) {
                float4 a = __ldg(&xr[ii]);
                float4 b = __ldg(&er[ii]);
                dot = fmaf(a.x, b.x, dot);
                dot = fmaf(a.y, b.y, dot);
                dot = fmaf(a.z, b.z, dot);
                dot = fmaf(a.w, b.w, dot);
            }
            float sc = fmaf(2.f, dot, -__ldg(&g_esq[kc]));
            if (sc > bs || (sc == bs && kc < bk)) { bs = sc; bk = kc; }
        }
        sIdx[t] = bk;
        out[IDX_OFF + o0 + t] = (float)bk;
        atomicAdd(&g_counts[bk], 1.0f);
    }
    __syncthreads();

    // ---- fused quantize / loss / dw on owned rows (warps 0..7: d = t) ----
    if (w < 8) {
        float lsum = 0.f;
        const float* xg = x + (size_t)o0 * DIM + t;
        float* qg = out + (size_t)o0 * DIM + t;
        const float* ecol = emb + (size_t)t * KCODES;
        float* dwcol = g_dw + (size_t)t * KCODES;
#pragma unroll 4
        for (int j = 0; j < nown; ++j) {
            const int bi = sIdx[j];
            float xv = xg[(size_t)j * DIM];
            float qv = __ldg(&ecol[bi]);
            float df = qv - xv;
            qg[(size_t)j * DIM] = xv + df;
            lsum += df * df;
            atomicAdd(&dwcol[bi], xv);
        }
#pragma unroll
        for (int o = 16; o > 0; o >>= 1) lsum += __shfl_xor_sync(0xffffffffu, lsum, o);
        if (l == 0) atomicAdd(&g_loss, lsum);
    }
}

// ---------------- finalize ----------------
__global__ void finalize_kernel(const float* __restrict__ ema_cs,
                                const int* __restrict__ counter,
                                float* __restrict__ out) {
    __shared__ float s_avg[KCODES];
    __shared__ float wn[8], wp[8], s_n;
    const int tid = threadIdx.x;
    const float debias = (float)(1.0 - pow(0.99, (double)(*counter + 1)));
    float nsum = 0.f, psum = 0.f;
    for (int i = tid; i < KCODES; i += 256) {
        float cnt = g_counts[i];
        float avg = (ema_cs[i] * DECAYF + cnt * OMD) / debias;
        s_avg[i] = avg; nsum += avg;
        float p = cnt * (1.0f / 16384.0f);
        psum += p * logf(p + 1e-10f);
    }
#pragma unroll
    for (int o = 16; o > 0; o >>= 1) {
        nsum += __shfl_xor_sync(0xffffffffu, nsum, o);
        psum += __shfl_xor_sync(0xffffffffu, psum, o);
    }
    if ((tid & 31) == 0) { wn[tid >> 5] = nsum; wp[tid >> 5] = psum; }
    __syncthreads();
    if (tid == 0) {
        float n = 0.f, ps = 0.f;
#pragma unroll
        for (int ww = 0; ww < 8; ++ww) { n += wn[ww]; ps += wp[ww]; }
        s_n = n;
        out[LOSS_OFF] = 0.25f * (g_loss / 4194304.0f);
        out[PERP_OFF] = expf(-ps);
    }
    __syncthreads();
    const float n = s_n, denom = n + KEPS;
    for (int i = tid; i < KCODES; i += 256)
        g_scale[i] = 1.0f / (debias * (((s_avg[i] + 1e-5f) / denom) * n));
}

// ---------------- new_embeddings ----------------
__global__ void emb_out_kernel(const float* __restrict__ ema_dw,
                               const float* __restrict__ emb,
                               const int* __restrict__ istrain,
                               float* __restrict__ out_emb) {
    const int i = blockIdx.x * 256 + threadIdx.x;
    out_emb[i] = (*istrain)
        ? (ema_dw[i] * DECAYF + g_dw[i] * OMD) * g_scale[i & (KCODES - 1)]
        : emb[i];
}

// ---------------- host launch ----------------
extern "C" void kernel_launch(void* const* d_in, const int* in_sizes, int n_in,
                              void* d_out, int out_size) {
    const float* x       = (const float*)d_in[0];
    const float* emb     = (const float*)d_in[1];
    const float* ema_cs  = (const float*)d_in[2];
    const float* ema_dw  = (const float*)d_in[3];
    const int*   counter = (const int*)d_in[4];
    const int*   istrain = (const int*)d_in[5];
    float* out = (float*)d_out;

    void *p_dw, *p_cnt, *p_loss;
    cudaGetSymbolAddress(&p_dw, g_dw);
    cudaGetSymbolAddress(&p_cnt, g_counts);
    cudaGetSymbolAddress(&p_loss, g_loss);
    cudaMemsetAsync(p_dw, 0, sizeof(float) * DIM * KCODES, 0);
    cudaMemsetAsync(p_cnt, 0, sizeof(float) * KCODES, 0);
    cudaMemsetAsync(p_loss, 0, sizeof(float), 0);

    cudaFuncSetAttribute(vq_hmma, cudaFuncAttributeMaxDynamicSharedMemorySize, SMEM_MAIN);

    prep_all<<<6176, 256>>>(x, emb);
    vq_hmma<<<NCTA, NTHR, SMEM_MAIN>>>(x, emb, out);
    finalize_kernel<<<1, 256>>>(ema_cs, counter, out);
    emb_out_kernel<<<(DIM * KCODES) / 256, 256>>>(ema_dw, emb, istrain, out + EMB_OFF);
}

// round 16
// speedup vs baseline: 1.8313x; 1.0254x over previous
#include <cuda_runtime.h>
#include <cuda_bf16.h>
#include <cstdint>
#include <math.h>
#include <float.h>

#define KCODES 8192
#define DIM    256
#define NROWS  16384
#define NCTA   148
#define MWIN   112                      // rows computed per CTA (window)
#define NTHR   448                      // 14 warps

#define Q_OFF     0
#define LOSS_OFF  4194304
#define PERP_OFF  4194305
#define IDX_OFF   4194306
#define EMB_OFF   4210690

#define DECAYF 0.99f
#define OMD    ((float)(1.0 - 0.99))
#define KEPS   ((float)(8192.0 * 1e-5))
#define MARGIN 0.3f

// smem geometry (bf16 tiles, 560B padded rows -> conflict-free ldmatrix)
#define PB      560
#define BUFSZ   (64 * PB)               // 35840
#define SOFF_B  (MWIN * PB)             // 62720
#define SOFF_ESQ (SOFF_B + 4 * BUFSZ)   // 206080
#define SMEM_MAIN (SOFF_ESQ + 4 * 256)  // 207104

// ---------------- device scratch (16B-aligned for float4/cp.async) ----------------
__device__ __align__(16) __nv_bfloat16 g_Bc[(size_t)KCODES * DIM];   // 4 MB code-major
__device__ __align__(16) float g_ET[(size_t)KCODES * DIM];           // 8 MB fp32 code-major
__device__ __align__(16) float g_esq[KCODES];
__device__ __align__(16) float g_dw[DIM * KCODES];
__device__ __align__(16) float g_counts[KCODES];
__device__ __align__(16) float g_scale[KCODES];
__device__ float g_loss;

// ---------------- PTX helpers ----------------
__device__ __forceinline__ uint32_t s2u(const void* p) {
    uint32_t a;
    asm("{ .reg .u64 t; cvta.to.shared.u64 t, %1; cvt.u32.u64 %0, t; }" : "=r"(a) : "l"(p));
    return a;
}
__device__ __forceinline__ void cpa16(uint32_t dst, const void* src) {
    asm volatile("cp.async.cg.shared.global [%0], [%1], 16;" :: "r"(dst), "l"(src) : "memory");
}
__device__ __forceinline__ void cpcommit() {
    asm volatile("cp.async.commit_group;" ::: "memory");
}
template <int N> __device__ __forceinline__ void cpwait() {
    asm volatile("cp.async.wait_group %0;" :: "n"(N) : "memory");
}
__device__ __forceinline__ void ldsm4(unsigned& r0, unsigned& r1, unsigned& r2, unsigned& r3,
                                      uint32_t a) {
    asm volatile("ldmatrix.sync.aligned.m8n8.x4.shared.b16 {%0,%1,%2,%3},[%4];"
                 : "=r"(r0), "=r"(r1), "=r"(r2), "=r"(r3) : "r"(a));
}
__device__ __forceinline__ void mma_bf16(float (&d)[4], const unsigned (&a)[4],
                                         const unsigned b0, const unsigned b1) {
    asm volatile("mma.sync.aligned.m16n8k16.row.col.f32.bf16.bf16.f32 "
                 "{%0,%1,%2,%3},{%4,%5,%6,%7},{%8,%9},{%0,%1,%2,%3};"
                 : "+f"(d[0]), "+f"(d[1]), "+f"(d[2]), "+f"(d[3])
                 : "r"(a[0]), "r"(a[1]), "r"(a[2]), "r"(a[3]), "r"(b0), "r"(b1));
}
__device__ __forceinline__ void top4(float s, int k, float (&S)[4], int (&I)[4]) {
    if (s > S[3]) {
        if (s > S[1]) {
            if (s > S[0]) {
                S[3] = S[2]; I[3] = I[2]; S[2] = S[1]; I[2] = I[1];
                S[1] = S[0]; I[1] = I[0]; S[0] = s; I[0] = k;
            } else {
                S[3] = S[2]; I[3] = I[2]; S[2] = S[1]; I[2] = I[1];
                S[1] = s; I[1] = k;
            }
        } else {
            if (s > S[2]) { S[3] = S[2]; I[3] = I[2]; S[2] = s; I[2] = k; }
            else          { S[3] = s; I[3] = k; }
        }
    }
}

// ---------------- merged prepass kernel ----------------
// bid < 2048          : transpose emb -> g_ET (fp32) + g_Bc (bf16), 32x32 tiles
// 2048 <= bid < 2080  : esq (deterministic column sums)
__global__ void prep_all(const float* __restrict__ emb) {
    __shared__ float tile[32][33];
    const int bid = blockIdx.x, t = threadIdx.x;
    if (bid < 2048) {
        const int k0 = (bid >> 3) * 32, d0 = (bid & 7) * 32;
        const int tx = t & 31, ty = t >> 5;
#pragma unroll
        for (int i = 0; i < 4; ++i)
            tile[ty + 8 * i][tx] = emb[(size_t)(d0 + ty + 8 * i) * KCODES + k0 + tx];
        __syncthreads();
#pragma unroll
        for (int i = 0; i < 4; ++i) {
            int kl = ty + 8 * i;
            float v = tile[tx][kl];
            size_t o = (size_t)(k0 + kl) * DIM + d0 + tx;
            g_ET[o] = v;
            g_Bc[o] = __float2bfloat16(v);
        }
    } else {
        int k = (bid - 2048) * 256 + t;
        float s = 0.f;
#pragma unroll 8
        for (int d = 0; d < DIM; ++d) {
            float v = __ldg(&emb[(size_t)d * KCODES + k]);
            s = fmaf(v, v, s);
        }
        g_esq[k] = s;
    }
}

// ---------------- main kernel ----------------
__device__ __forceinline__ void issueB(uint32_t sb, int t, int c, int buf) {
    const char* src = (const char*)g_Bc + (size_t)c * 64 * 512;
    const uint32_t dst = sb + SOFF_B + buf * BUFSZ;
#pragma unroll
    for (int i = 0; i < 5; ++i) {          // ceil(2048/448) = 5
        int q = t + NTHR * i;               // 2048 16B transfers total
        if (q < 2048) {
            int r = q >> 5, o = q & 31;
            cpa16(dst + r * PB + o * 16, src + (size_t)r * 512 + o * 16);
        }
    }
    if (t < 16)
        cpa16(sb + SOFF_ESQ + buf * 256 + t * 16, (const char*)g_esq + c * 256 + t * 16);
}

__global__ void __launch_bounds__(NTHR, 1)
vq_hmma(const float* __restrict__ x, const float* __restrict__ emb,
        float* __restrict__ out) {
    extern __shared__ char sm[];
    const uint32_t sb = s2u(sm);
    const int t = threadIdx.x, l = t & 31, w = t >> 5;   // 14 warps
    const int g = w >> 1, h = w & 1;                     // row-group 0..6, code-half
    const int bid = blockIdx.x;
    const int o0 = (int)(((long long)bid * NROWS) / NCTA);
    const int o1 = (int)(((long long)(bid + 1) * NROWS) / NCTA);
    const int w0 = (o0 > NROWS - MWIN) ? (NROWS - MWIN) : o0;
    const int nown = o1 - o0;

    // ---- B prologue: chunks 0..2 (start async loads first) ----
#pragma unroll
    for (int p = 0; p < 3; ++p) { issueB(sb, t, p, p); cpcommit(); }

    // ---- stage A window: fp32 x -> bf16 smem (fused, no prepass) ----
    {
        const float4* asrc = (const float4*)(x + (size_t)w0 * DIM);
#pragma unroll
        for (int i = 0; i < 16; ++i) {
            int q = t + NTHR * i;            // 7168 = 448*16 float4s exactly
            int r = q >> 6, o = q & 63;
            float4 v = __ldg(&asrc[q]);
            __nv_bfloat162 lo = __floats2bfloat162_rn(v.x, v.y);
            __nv_bfloat162 hi = __floats2bfloat162_rn(v.z, v.w);
            uint2 pk;
            pk.x = *(unsigned*)&lo; pk.y = *(unsigned*)&hi;
            *(uint2*)(sm + r * PB + o * 8) = pk;
        }
    }
    __syncthreads();

    // ---- A fragments: 16 rows per warp ----
    unsigned aF[16][4];
    {
        uint32_t ab = sb + (g * 16 + (l & 15)) * PB + (l >> 4) * 16;
#pragma unroll
        for (int kt = 0; kt < 16; ++kt)
            ldsm4(aF[kt][0], aF[kt][1], aF[kt][2], aF[kt][3], ab + kt * 32);
    }

    float acc[4][4];
#pragma unroll
    for (int n = 0; n < 4; ++n)
#pragma unroll
        for (int j = 0; j < 4; ++j) acc[n][j] = 0.f;

    float Sa[4], Sb2[4];
    int   Ia[4], Ib[4];
#pragma unroll
    for (int j = 0; j < 4; ++j) {
        Sa[j] = -FLT_MAX; Sb2[j] = -FLT_MAX; Ia[j] = 0; Ib[j] = 0;
    }

    const uint32_t laneB = (uint32_t)(h * 32 + (l & 7) + ((l >> 4) << 3)) * PB
                         + ((l >> 3) & 1) * 16;
    const int q2 = (l & 3) * 2;

    // ---- stream 128 chunks of 64 codes; 4 buffers, ONE barrier per chunk ----
#pragma unroll 1
    for (int c = 0; c < 128; ++c) {
        const int buf = c & 3;
        __syncthreads();                        // all warps done consuming chunk c-1
        if (c + 3 < 128) issueB(sb, t, c + 3, (c + 3) & 3);   // overwrites (c-1)&3: safe
        cpcommit();                             // unconditional: keeps group count uniform
        cpwait<3>();                            // chunk c resident
        const uint32_t bb = sb + SOFF_B + buf * BUFSZ + laneB;
#pragma unroll
        for (int kt = 0; kt < 16; ++kt) {
            unsigned b[4][2];
#pragma unroll
            for (int p = 0; p < 2; ++p)
                ldsm4(b[2 * p][0], b[2 * p][1], b[2 * p + 1][0], b[2 * p + 1][1],
                      bb + p * (16 * PB) + kt * 32);
#pragma unroll
            for (int n = 0; n < 4; ++n)
                mma_bf16(acc[n], aF[kt], b[n][0], b[n][1]);
        }
        const float* eSq = (const float*)(sm + SOFF_ESQ + buf * 256);
        const int cb = c * 64 + h * 32 + q2;
#pragma unroll
        for (int n = 0; n < 4; ++n) {
            float2 ev = *(const float2*)&eSq[h * 32 + n * 8 + q2];
            const int k0 = cb + n * 8;
            top4(fmaf(2.f, acc[n][0], -ev.x), k0,     Sa,  Ia);
            top4(fmaf(2.f, acc[n][1], -ev.y), k0 + 1, Sa,  Ia);
            top4(fmaf(2.f, acc[n][2], -ev.x), k0,     Sb2, Ib);
            top4(fmaf(2.f, acc[n][3], -ev.y), k0 + 1, Sb2, Ib);
            acc[n][0] = 0.f; acc[n][1] = 0.f; acc[n][2] = 0.f; acc[n][3] = 0.f;
        }
    }
    cpwait<0>();

    // ---- dump candidates: 32 per window row ----
    int*   cand = (int*)sm;                 // 112*32*4 = 14336
    float* sco  = (float*)(sm + 14336);     // 14336
    int*   sIdx = (int*)(sm + 28672);       // 112 ints
    __syncthreads();                        // mainloop fully done before smem reuse
    {
        const int rA = g * 16 + (l >> 2), rB = rA + 8;
        const int s0 = h * 16 + (l & 3) * 4;
#pragma unroll
        for (int j = 0; j < 4; ++j) {
            cand[rA * 32 + s0 + j] = Ia[j];
            sco [rA * 32 + s0 + j] = Sa[j];
            cand[rB * 32 + s0 + j] = Ib[j];
            sco [rB * 32 + s0 + j] = Sb2[j];
        }
    }
    __syncthreads();

    // ---- selection on OWNED rows: margin filter + exact sequential-d rescore ----
    if (t < nown) {
        const int wr = (o0 - w0) + t;       // window-relative row
        float m = -FLT_MAX;
#pragma unroll
        for (int s = 0; s < 32; ++s) m = fmaxf(m, sco[wr * 32 + s]);
        const float thr = m - MARGIN;
        const float4* xr = (const float4*)(x + (size_t)(o0 + t) * DIM);
        float bs = -FLT_MAX; int bk = 0x7fffffff;
#pragma unroll 1
        for (int s = 0; s < 32; ++s) {
            if (sco[wr * 32 + s] < thr) continue;
            const int kc = cand[wr * 32 + s];
            const float4* er = (const float4*)(g_ET + (size_t)kc * DIM);
            float dot = 0.f;
#pragma unroll 8
            for (int ii = 0; ii < 64; ++ii) {
                float4 a = __ldg(&xr[ii]);
                float4 b = __ldg(&er[ii]);
                dot = fmaf(a.x, b.x, dot);
                dot = fmaf(a.y, b.y, dot);
                dot = fmaf(a.z, b.z, dot);
                dot = fmaf(a.w, b.w, dot);
            }
            float sc = fmaf(2.f, dot, -__ldg(&g_esq[kc]));
            if (sc > bs || (sc == bs && kc < bk)) { bs = sc; bk = kc; }
        }
        sIdx[t] = bk;
        out[IDX_OFF + o0 + t] = (float)bk;
        atomicAdd(&g_counts[bk], 1.0f);
    }
    __syncthreads();

    // ---- fused quantize / loss / dw on owned rows (warps 0..7: d = t) ----
    if (w < 8) {
        float lsum = 0.f;
        const float* xg = x + (size_t)o0 * DIM + t;
        float* qg = out + (size_t)o0 * DIM + t;
        const float* ecol = emb + (size_t)t * KCODES;
        float* dwcol = g_dw + (size_t)t * KCODES;
#pragma unroll 4
        for (int j = 0; j < nown; ++j) {
            const int bi = sIdx[j];
            float xv = xg[(size_t)j * DIM];
            float qv = __ldg(&ecol[bi]);
            float df = qv - xv;
            qg[(size_t)j * DIM] = xv + df;
            lsum += df * df;
            atomicAdd(&dwcol[bi], xv);
        }
#pragma unroll
        for (int o = 16; o > 0; o >>= 1) lsum += __shfl_xor_sync(0xffffffffu, lsum, o);
        if (l == 0) atomicAdd(&g_loss, lsum);
    }
}

// ---------------- finalize ----------------
__global__ void finalize_kernel(const float* __restrict__ ema_cs,
                                const int* __restrict__ counter,
                                float* __restrict__ out) {
    __shared__ float s_avg[KCODES];
    __shared__ float wn[8], wp[8], s_n;
    const int tid = threadIdx.x;
    const float debias = (float)(1.0 - pow(0.99, (double)(*counter + 1)));
    float nsum = 0.f, psum = 0.f;
    for (int i = tid; i < KCODES; i += 256) {
        float cnt = g_counts[i];
        float avg = (ema_cs[i] * DECAYF + cnt * OMD) / debias;
        s_avg[i] = avg; nsum += avg;
        float p = cnt * (1.0f / 16384.0f);
        psum += p * logf(p + 1e-10f);
    }
#pragma unroll
    for (int o = 16; o > 0; o >>= 1) {
        nsum += __shfl_xor_sync(0xffffffffu, nsum, o);
        psum += __shfl_xor_sync(0xffffffffu, psum, o);
    }
    if ((tid & 31) == 0) { wn[tid >> 5] = nsum; wp[tid >> 5] = psum; }
    __syncthreads();
    if (tid == 0) {
        float n = 0.f, ps = 0.f;
#pragma unroll
        for (int ww = 0; ww < 8; ++ww) { n += wn[ww]; ps += wp[ww]; }
        s_n = n;
        out[LOSS_OFF] = 0.25f * (g_loss / 4194304.0f);
        out[PERP_OFF] = expf(-ps);
    }
    __syncthreads();
    const float n = s_n, denom = n + KEPS;
    for (int i = tid; i < KCODES; i += 256)
        g_scale[i] = 1.0f / (debias * (((s_avg[i] + 1e-5f) / denom) * n));
}

// ---------------- new_embeddings (float4 loads, float2 stores: out_emb is
// only 8B-aligned — out + EMB_OFF, EMB_OFF % 4 == 2) ----------------
__global__ void emb_out_kernel(const float* __restrict__ ema_dw,
                               const float* __restrict__ emb,
                               const int* __restrict__ istrain,
                               float* __restrict__ out_emb) {
    const int i = blockIdx.x * 256 + threadIdx.x;        // float4 index
    float2* dst = (float2*)(out_emb + (size_t)i * 4);
    if (*istrain) {
        float4 dw = ((const float4*)g_dw)[i];
        float4 ed = __ldg(&((const float4*)ema_dw)[i]);
        const int kb = (i * 4) & (KCODES - 1);           // 4-aligned within 8192 row
        float4 sc = *(const float4*)&g_scale[kb];
        float2 r0, r1;
        r0.x = (ed.x * DECAYF + dw.x * OMD) * sc.x;
        r0.y = (ed.y * DECAYF + dw.y * OMD) * sc.y;
        r1.x = (ed.z * DECAYF + dw.z * OMD) * sc.z;
        r1.y = (ed.w * DECAYF + dw.w * OMD) * sc.w;
        dst[0] = r0;
        dst[1] = r1;
    } else {
        float4 e = __ldg(&((const float4*)emb)[i]);
        dst[0] = make_float2(e.x, e.y);
        dst[1] = make_float2(e.z, e.w);
    }
}

// ---------------- host launch ----------------
extern "C" void kernel_launch(void* const* d_in, const int* in_sizes, int n_in,
                              void* d_out, int out_size) {
    const float* x       = (const float*)d_in[0];
    const float* emb     = (const float*)d_in[1];
    const float* ema_cs  = (const float*)d_in[2];
    const float* ema_dw  = (const float*)d_in[3];
    const int*   counter = (const int*)d_in[4];
    const int*   istrain = (const int*)d_in[5];
    float* out = (float*)d_out;

    void *p_dw, *p_cnt, *p_loss;
    cudaGetSymbolAddress(&p_dw, g_dw);
    cudaGetSymbolAddress(&p_cnt, g_counts);
    cudaGetSymbolAddress(&p_loss, g_loss);
    cudaMemsetAsync(p_dw, 0, sizeof(float) * DIM * KCODES, 0);
    cudaMemsetAsync(p_cnt, 0, sizeof(float) * KCODES, 0);
    cudaMemsetAsync(p_loss, 0, sizeof(float), 0);

    cudaFuncSetAttribute(vq_hmma, cudaFuncAttributeMaxDynamicSharedMemorySize, SMEM_MAIN);

    prep_all<<<2080, 256>>>(emb);
    vq_hmma<<<NCTA, NTHR, SMEM_MAIN>>>(x, emb, out);
    finalize_kernel<<<1, 256>>>(ema_cs, counter, out);
    emb_out_kernel<<<(DIM * KCODES / 4) / 256, 256>>>(ema_dw, emb, istrain, out + EMB_OFF);
}

// round 17
// speedup vs baseline: 1.8734x; 1.0230x over previous
#include <cuda_runtime.h>
#include <cuda_fp16.h>
#include <cstdint>
#include <math.h>
#include <float.h>

#define KCODES 8192
#define DIM    256
#define NROWS  16384
#define NCTA   148
#define MWIN   112                      // rows computed per CTA (window)
#define NTHR   448                      // 14 warps

#define Q_OFF     0
#define LOSS_OFF  4194304
#define PERP_OFF  4194305
#define IDX_OFF   4194306
#define EMB_OFF   4210690

#define DECAYF 0.99f
#define OMD    ((float)(1.0 - 0.99))
#define KEPS   ((float)(8192.0 * 1e-5))
#define MARGIN 0.3f

// smem geometry (fp16 tiles, 560B padded rows -> conflict-free ldmatrix)
#define PB      560
#define BUFSZ   (64 * PB)               // 35840
#define SOFF_B  (MWIN * PB)             // 62720
#define SOFF_ESQ (SOFF_B + 4 * BUFSZ)   // 206080
#define SMEM_MAIN (SOFF_ESQ + 4 * 256)  // 207104

// ---------------- device scratch (16B-aligned for float4/cp.async) ----------------
__device__ __align__(16) __half g_Bc[(size_t)KCODES * DIM];          // 4 MB code-major fp16
__device__ __align__(16) float g_ET[(size_t)KCODES * DIM];           // 8 MB fp32 code-major
__device__ __align__(16) float g_esq[KCODES];
__device__ __align__(16) float g_dw[DIM * KCODES];
__device__ __align__(16) float g_counts[KCODES];
__device__ __align__(16) float g_scale[KCODES];
__device__ float g_loss;

// ---------------- PTX helpers ----------------
__device__ __forceinline__ uint32_t s2u(const void* p) {
    uint32_t a;
    asm("{ .reg .u64 t; cvta.to.shared.u64 t, %1; cvt.u32.u64 %0, t; }" : "=r"(a) : "l"(p));
    return a;
}
__device__ __forceinline__ void cpa16(uint32_t dst, const void* src) {
    asm volatile("cp.async.cg.shared.global [%0], [%1], 16;" :: "r"(dst), "l"(src) : "memory");
}
__device__ __forceinline__ void cpcommit() {
    asm volatile("cp.async.commit_group;" ::: "memory");
}
template <int N> __device__ __forceinline__ void cpwait() {
    asm volatile("cp.async.wait_group %0;" :: "n"(N) : "memory");
}
__device__ __forceinline__ void ldsm4(unsigned& r0, unsigned& r1, unsigned& r2, unsigned& r3,
                                      uint32_t a) {
    asm volatile("ldmatrix.sync.aligned.m8n8.x4.shared.b16 {%0,%1,%2,%3},[%4];"
                 : "=r"(r0), "=r"(r1), "=r"(r2), "=r"(r3) : "r"(a));
}
// fp16 in, fp16 accumulate: D/C = 2 regs of f16x2; reg0={d0,d1} (row r), reg1={d2,d3} (row r+8)
__device__ __forceinline__ void mma_f16acc(unsigned (&d)[2], const unsigned (&a)[4],
                                           const unsigned b0, const unsigned b1) {
    asm volatile("mma.sync.aligned.m16n8k16.row.col.f16.f16.f16.f16 "
                 "{%0,%1},{%2,%3,%4,%5},{%6,%7},{%0,%1};"
                 : "+r"(d[0]), "+r"(d[1])
                 : "r"(a[0]), "r"(a[1]), "r"(a[2]), "r"(a[3]), "r"(b0), "r"(b1));
}
__device__ __forceinline__ void top4(float s, int k, float (&S)[4], int (&I)[4]) {
    if (s > S[3]) {
        if (s > S[1]) {
            if (s > S[0]) {
                S[3] = S[2]; I[3] = I[2]; S[2] = S[1]; I[2] = I[1];
                S[1] = S[0]; I[1] = I[0]; S[0] = s; I[0] = k;
            } else {
                S[3] = S[2]; I[3] = I[2]; S[2] = S[1]; I[2] = I[1];
                S[1] = s; I[1] = k;
            }
        } else {
            if (s > S[2]) { S[3] = S[2]; I[3] = I[2]; S[2] = s; I[2] = k; }
            else          { S[3] = s; I[3] = k; }
        }
    }
}

// ---------------- merged prepass kernel (also zeroes scratch; no memsets) ----------------
// [0,2048)    : transpose emb -> g_ET (fp32) + g_Bc (fp16), 32x32 tiles
// [2048,2080) : esq (deterministic column sums)
// [2080,4128) : zero g_dw (float4)
// [4128,4136) : zero g_counts (float4)
// 4136        : zero g_loss
__global__ void prep_all(const float* __restrict__ emb) {
    __shared__ float tile[32][33];
    const int bid = blockIdx.x, t = threadIdx.x;
    if (bid < 2048) {
        const int k0 = (bid >> 3) * 32, d0 = (bid & 7) * 32;
        const int tx = t & 31, ty = t >> 5;
#pragma unroll
        for (int i = 0; i < 4; ++i)
            tile[ty + 8 * i][tx] = emb[(size_t)(d0 + ty + 8 * i) * KCODES + k0 + tx];
        __syncthreads();
#pragma unroll
        for (int i = 0; i < 4; ++i) {
            int kl = ty + 8 * i;
            float v = tile[tx][kl];
            size_t o = (size_t)(k0 + kl) * DIM + d0 + tx;
            g_ET[o] = v;
            g_Bc[o] = __float2half_rn(v);
        }
    } else if (bid < 2080) {
        int k = (bid - 2048) * 256 + t;
        float s = 0.f;
#pragma unroll 8
        for (int d = 0; d < DIM; ++d) {
            float v = __ldg(&emb[(size_t)d * KCODES + k]);
            s = fmaf(v, v, s);
        }
        g_esq[k] = s;
    } else if (bid < 4128) {
        ((float4*)g_dw)[(size_t)(bid - 2080) * 256 + t] = make_float4(0.f, 0.f, 0.f, 0.f);
    } else if (bid < 4136) {
        ((float4*)g_counts)[(bid - 4128) * 256 + t] = make_float4(0.f, 0.f, 0.f, 0.f);
    } else {
        if (t == 0) g_loss = 0.f;
    }
}

// ---------------- main kernel ----------------
__device__ __forceinline__ void issueB(uint32_t sb, int t, int c, int buf) {
    const char* src = (const char*)g_Bc + (size_t)c * 64 * 512;
    const uint32_t dst = sb + SOFF_B + buf * BUFSZ;
#pragma unroll
    for (int i = 0; i < 5; ++i) {          // ceil(2048/448) = 5
        int q = t + NTHR * i;               // 2048 16B transfers total
        if (q < 2048) {
            int r = q >> 5, o = q & 31;
            cpa16(dst + r * PB + o * 16, src + (size_t)r * 512 + o * 16);
        }
    }
    if (t < 16)
        cpa16(sb + SOFF_ESQ + buf * 256 + t * 16, (const char*)g_esq + c * 256 + t * 16);
}

__global__ void __launch_bounds__(NTHR, 1)
vq_hmma(const float* __restrict__ x, const float* __restrict__ emb,
        float* __restrict__ out) {
    extern __shared__ char sm[];
    const uint32_t sb = s2u(sm);
    const int t = threadIdx.x, l = t & 31, w = t >> 5;   // 14 warps
    const int g = w >> 1, h = w & 1;                     // row-group 0..6, code-half
    const int bid = blockIdx.x;
    const int o0 = (int)(((long long)bid * NROWS) / NCTA);
    const int o1 = (int)(((long long)(bid + 1) * NROWS) / NCTA);
    const int w0 = (o0 > NROWS - MWIN) ? (NROWS - MWIN) : o0;
    const int nown = o1 - o0;

    // ---- B prologue: chunks 0..2 (start async loads first) ----
#pragma unroll
    for (int p = 0; p < 3; ++p) { issueB(sb, t, p, p); cpcommit(); }

    // ---- stage A window: fp32 x -> fp16 smem ----
    {
        const float4* asrc = (const float4*)(x + (size_t)w0 * DIM);
#pragma unroll
        for (int i = 0; i < 16; ++i) {
            int q = t + NTHR * i;            // 7168 = 448*16 float4s exactly
            int r = q >> 6, o = q & 63;
            float4 v = __ldg(&asrc[q]);
            __half2 lo = __floats2half2_rn(v.x, v.y);
            __half2 hi = __floats2half2_rn(v.z, v.w);
            uint2 pk;
            pk.x = *(unsigned*)&lo; pk.y = *(unsigned*)&hi;
            *(uint2*)(sm + r * PB + o * 8) = pk;
        }
    }
    __syncthreads();

    // ---- A fragments: 16 rows per warp ----
    unsigned aF[16][4];
    {
        uint32_t ab = sb + (g * 16 + (l & 15)) * PB + (l >> 4) * 16;
#pragma unroll
        for (int kt = 0; kt < 16; ++kt)
            ldsm4(aF[kt][0], aF[kt][1], aF[kt][2], aF[kt][3], ab + kt * 32);
    }

    unsigned acc[4][2];
#pragma unroll
    for (int n = 0; n < 4; ++n) { acc[n][0] = 0u; acc[n][1] = 0u; }

    float Sa[4], Sb2[4];
    int   Ia[4], Ib[4];
#pragma unroll
    for (int j = 0; j < 4; ++j) {
        Sa[j] = -FLT_MAX; Sb2[j] = -FLT_MAX; Ia[j] = 0; Ib[j] = 0;
    }

    const uint32_t laneB = (uint32_t)(h * 32 + (l & 7) + ((l >> 4) << 3)) * PB
                         + ((l >> 3) & 1) * 16;
    const int q2 = (l & 3) * 2;

    // ---- stream 128 chunks of 64 codes; 4 buffers, ONE barrier per chunk ----
#pragma unroll 1
    for (int c = 0; c < 128; ++c) {
        const int buf = c & 3;
        __syncthreads();                        // all warps done consuming chunk c-1
        if (c + 3 < 128) issueB(sb, t, c + 3, (c + 3) & 3);   // overwrites (c-1)&3: safe
        cpcommit();                             // unconditional: keeps group count uniform
        cpwait<3>();                            // chunk c resident
        const uint32_t bb = sb + SOFF_B + buf * BUFSZ + laneB;
#pragma unroll
        for (int kt = 0; kt < 16; ++kt) {
            unsigned b[4][2];
#pragma unroll
            for (int p = 0; p < 2; ++p)
                ldsm4(b[2 * p][0], b[2 * p][1], b[2 * p + 1][0], b[2 * p + 1][1],
                      bb + p * (16 * PB) + kt * 32);
#pragma unroll
            for (int n = 0; n < 4; ++n)
                mma_f16acc(acc[n], aF[kt], b[n][0], b[n][1]);
        }
        const float* eSq = (const float*)(sm + SOFF_ESQ + buf * 256);
        const int cb = c * 64 + h * 32 + q2;
#pragma unroll
        for (int n = 0; n < 4; ++n) {
            float2 ev = *(const float2*)&eSq[h * 32 + n * 8 + q2];
            const int k0 = cb + n * 8;
            float2 lo = __half22float2(*(__half2*)&acc[n][0]);   // row rA: d0,d1
            float2 hi = __half22float2(*(__half2*)&acc[n][1]);   // row rB: d2,d3
            top4(fmaf(2.f, lo.x, -ev.x), k0,     Sa,  Ia);
            top4(fmaf(2.f, lo.y, -ev.y), k0 + 1, Sa,  Ia);
            top4(fmaf(2.f, hi.x, -ev.x), k0,     Sb2, Ib);
            top4(fmaf(2.f, hi.y, -ev.y), k0 + 1, Sb2, Ib);
            acc[n][0] = 0u; acc[n][1] = 0u;
        }
    }
    cpwait<0>();

    // ---- dump candidates: 32 per window row ----
    int*   cand = (int*)sm;                 // 112*32*4 = 14336
    float* sco  = (float*)(sm + 14336);     // 14336
    int*   sIdx = (int*)(sm + 28672);       // 112 ints
    __syncthreads();                        // mainloop fully done before smem reuse
    {
        const int rA = g * 16 + (l >> 2), rB = rA + 8;
        const int s0 = h * 16 + (l & 3) * 4;
#pragma unroll
        for (int j = 0; j < 4; ++j) {
            cand[rA * 32 + s0 + j] = Ia[j];
            sco [rA * 32 + s0 + j] = Sa[j];
            cand[rB * 32 + s0 + j] = Ib[j];
            sco [rB * 32 + s0 + j] = Sb2[j];
        }
    }
    __syncthreads();

    // ---- selection on OWNED rows: margin filter + exact sequential-d rescore ----
    if (t < nown) {
        const int wr = (o0 - w0) + t;       // window-relative row
        float m = -FLT_MAX;
#pragma unroll
        for (int s = 0; s < 32; ++s) m = fmaxf(m, sco[wr * 32 + s]);
        const float thr = m - MARGIN;
        const float4* xr = (const float4*)(x + (size_t)(o0 + t) * DIM);
        float bs = -FLT_MAX; int bk = 0x7fffffff;
#pragma unroll 1
        for (int s = 0; s < 32; ++s) {
            if (sco[wr * 32 + s] < thr) continue;
            const int kc = cand[wr * 32 + s];
            const float4* er = (const float4*)(g_ET + (size_t)kc * DIM);
            float dot = 0.f;
#pragma unroll 8
            for (int ii = 0; ii < 64; ++ii) {
                float4 a = __ldg(&xr[ii]);
                float4 b = __ldg(&er[ii]);
                dot = fmaf(a.x, b.x, dot);
                dot = fmaf(a.y, b.y, dot);
                dot = fmaf(a.z, b.z, dot);
                dot = fmaf(a.w, b.w, dot);
            }
            float sc = fmaf(2.f, dot, -__ldg(&g_esq[kc]));
            if (sc > bs || (sc == bs && kc < bk)) { bs = sc; bk = kc; }
        }
        sIdx[t] = bk;
        out[IDX_OFF + o0 + t] = (float)bk;
        atomicAdd(&g_counts[bk], 1.0f);
    }
    __syncthreads();

    // ---- fused quantize / loss / dw on owned rows (warps 0..7: d = t) ----
    if (w < 8) {
        float lsum = 0.f;
        const float* xg = x + (size_t)o0 * DIM + t;
        float* qg = out + (size_t)o0 * DIM + t;
        const float* ecol = emb + (size_t)t * KCODES;
        float* dwcol = g_dw + (size_t)t * KCODES;
#pragma unroll 4
        for (int j = 0; j < nown; ++j) {
            const int bi = sIdx[j];
            float xv = xg[(size_t)j * DIM];
            float qv = __ldg(&ecol[bi]);
            float df = qv - xv;
            qg[(size_t)j * DIM] = xv + df;
            lsum += df * df;
            atomicAdd(&dwcol[bi], xv);
        }
#pragma unroll
        for (int o = 16; o > 0; o >>= 1) lsum += __shfl_xor_sync(0xffffffffu, lsum, o);
        if (l == 0) atomicAdd(&g_loss, lsum);
    }
}

// ---------------- finalize ----------------
__global__ void finalize_kernel(const float* __restrict__ ema_cs,
                                const int* __restrict__ counter,
                                float* __restrict__ out) {
    __shared__ float s_avg[KCODES];
    __shared__ float wn[8], wp[8], s_n;
    const int tid = threadIdx.x;
    const float debias = (float)(1.0 - pow(0.99, (double)(*counter + 1)));
    float nsum = 0.f, psum = 0.f;
    for (int i = tid; i < KCODES; i += 256) {
        float cnt = g_counts[i];
        float avg = (ema_cs[i] * DECAYF + cnt * OMD) / debias;
        s_avg[i] = avg; nsum += avg;
        float p = cnt * (1.0f / 16384.0f);
        psum += p * logf(p + 1e-10f);
    }
#pragma unroll
    for (int o = 16; o > 0; o >>= 1) {
        nsum += __shfl_xor_sync(0xffffffffu, nsum, o);
        psum += __shfl_xor_sync(0xffffffffu, psum, o);
    }
    if ((tid & 31) == 0) { wn[tid >> 5] = nsum; wp[tid >> 5] = psum; }
    __syncthreads();
    if (tid == 0) {
        float n = 0.f, ps = 0.f;
#pragma unroll
        for (int ww = 0; ww < 8; ++ww) { n += wn[ww]; ps += wp[ww]; }
        s_n = n;
        out[LOSS_OFF] = 0.25f * (g_loss / 4194304.0f);
        out[PERP_OFF] = expf(-ps);
    }
    __syncthreads();
    const float n = s_n, denom = n + KEPS;
    for (int i = tid; i < KCODES; i += 256)
        g_scale[i] = 1.0f / (debias * (((s_avg[i] + 1e-5f) / denom) * n));
}

// ---------------- new_embeddings (float4 loads, float2 stores: out_emb only 8B-aligned) ----------------
__global__ void emb_out_kernel(const float* __restrict__ ema_dw,
                               const float* __restrict__ emb,
                               const int* __restrict__ istrain,
                               float* __restrict__ out_emb) {
    const int i = blockIdx.x * 256 + threadIdx.x;        // float4 index
    float2* dst = (float2*)(out_emb + (size_t)i * 4);
    if (*istrain) {
        float4 dw = ((const float4*)g_dw)[i];
        float4 ed = __ldg(&((const float4*)ema_dw)[i]);
        const int kb = (i * 4) & (KCODES - 1);           // 4-aligned within 8192 row
        float4 sc = *(const float4*)&g_scale[kb];
        float2 r0, r1;
        r0.x = (ed.x * DECAYF + dw.x * OMD) * sc.x;
        r0.y = (ed.y * DECAYF + dw.y * OMD) * sc.y;
        r1.x = (ed.z * DECAYF + dw.z * OMD) * sc.z;
        r1.y = (ed.w * DECAYF + dw.w * OMD) * sc.w;
        dst[0] = r0;
        dst[1] = r1;
    } else {
        float4 e = __ldg(&((const float4*)emb)[i]);
        dst[0] = make_float2(e.x, e.y);
        dst[1] = make_float2(e.z, e.w);
    }
}

// ---------------- host launch ----------------
extern "C" void kernel_launch(void* const* d_in, const int* in_sizes, int n_in,
                              void* d_out, int out_size) {
    const float* x       = (const float*)d_in[0];
    const float* emb     = (const float*)d_in[1];
    const float* ema_cs  = (const float*)d_in[2];
    const float* ema_dw  = (const float*)d_in[3];
    const int*   counter = (const int*)d_in[4];
    const int*   istrain = (const int*)d_in[5];
    float* out = (float*)d_out;

    cudaFuncSetAttribute(vq_hmma, cudaFuncAttributeMaxDynamicSharedMemorySize, SMEM_MAIN);

    prep_all<<<4137, 256>>>(emb);
    vq_hmma<<<NCTA, NTHR, SMEM_MAIN>>>(x, emb, out);
    finalize_kernel<<<1, 256>>>(ema_cs, counter, out);
    emb_out_kernel<<<(DIM * KCODES / 4) / 256, 256>>>(ema_dw, emb, istrain, out + EMB_OFF);
}